// round 7
// baseline (speedup 1.0000x reference)
#include <cuda_runtime.h>
#include <cstdint>
#include <math_constants.h>

#define COLS   24576
#define V4     (COLS / 4)      // 6144 float4 per row
#define NT     512             // threads per CTA
#define NW     (NT / 32)       // 16 warps
#define NBC    32              // coarse bins: key >> 27
#define NBF    4096            // fine bins:  (key >> 15) & 0xFFF
#define BPTF   (NBF / NT)      // 8 fine bins per thread in the scan
#define CAP    2048            // candidate buffer capacity (~560 expected)

// Order-preserving float->uint key: larger float => larger key.
__device__ __forceinline__ uint32_t fkey(float f) {
    uint32_t u = __float_as_uint(f);
    return u ^ (uint32_t)(((int32_t)u >> 31) | (int32_t)0x80000000);
}
// Inverse of fkey.
__device__ __forceinline__ float fkey_inv(uint32_t key) {
    uint32_t u = key ^ ((key & 0x80000000u) ? 0x80000000u : 0xFFFFFFFFu);
    return __uint_as_float(u);
}

__global__ __launch_bounds__(NT, 4) void topk_scatter_kernel(
    const float* __restrict__ z,
    const int*   __restrict__ kin,
    float*       __restrict__ out)
{
    __shared__ uint32_t coarse[NBC];       // 128 B
    __shared__ uint32_t fineH[NBF];        // 16 KB
    __shared__ uint32_t candKey[CAP];      // 8 KB
    __shared__ uint16_t candIdx[CAP];      // 4 KB
    __shared__ uint32_t warpTot[NW];
    __shared__ uint32_t s_B0, s_A0, s_cnt, s_B1, s_A1;

    const int tid  = threadIdx.x;
    const int lane = tid & 31;
    const int wid  = tid >> 5;
    const int row  = blockIdx.x;
    const uint32_t ltmask = (lane == 0) ? 0u : ((1u << lane) - 1u);
    const uint32_t k = (uint32_t)(kin ? *kin : 64);

    const float4* zr  = reinterpret_cast<const float4*>(z) + (size_t)row * V4;
    float4*       orw = reinterpret_cast<float4*>(out)     + (size_t)row * V4;
    float*        orow = out + (size_t)row * COLS;

    if (tid < NBC) coarse[tid] = 0;
    #pragma unroll
    for (int i = tid; i < NBF; i += NT) fineH[i] = 0;
    if (tid == 0) s_cnt = 0;
    __syncthreads();

    // ---- Pass 1 (HBM read): coarse 32-bin histogram, match-aggregated atomics ----
    #pragma unroll 1
    for (int i = tid; i < V4; i += NT) {
        float4 v = zr[i];
        uint32_t b0 = fkey(v.x) >> 27;
        uint32_t b1 = fkey(v.y) >> 27;
        uint32_t b2 = fkey(v.z) >> 27;
        uint32_t b3 = fkey(v.w) >> 27;
        uint32_t m0 = __match_any_sync(0xFFFFFFFFu, b0);
        if ((m0 & ltmask) == 0) atomicAdd(&coarse[b0], (uint32_t)__popc(m0));
        uint32_t m1 = __match_any_sync(0xFFFFFFFFu, b1);
        if ((m1 & ltmask) == 0) atomicAdd(&coarse[b1], (uint32_t)__popc(m1));
        uint32_t m2 = __match_any_sync(0xFFFFFFFFu, b2);
        if ((m2 & ltmask) == 0) atomicAdd(&coarse[b2], (uint32_t)__popc(m2));
        uint32_t m3 = __match_any_sync(0xFFFFFFFFu, b3);
        if ((m3 & ltmask) == 0) atomicAdd(&coarse[b3], (uint32_t)__popc(m3));
    }
    __syncthreads();

    // ---- Coarse suffix scan (warp 0): find coarse bin B0 holding rank k ----
    if (wid == 0) {
        uint32_t c = coarse[lane];
        uint32_t inc = c;
        #pragma unroll
        for (int off = 1; off < 32; off <<= 1) {
            uint32_t o = __shfl_down_sync(0xFFFFFFFFu, inc, off);
            if (lane + off < 32) inc += o;
        }
        uint32_t abv = inc - c;                 // count strictly above this bin
        if (abv < k && inc >= k) { s_B0 = (uint32_t)lane; s_A0 = abv; }
    }
    __syncthreads();
    const uint32_t B0 = s_B0;
    const uint32_t A0 = s_A0;

    // Float thresholds: bin(v) > B0  <=>  v >= hiThr ;  bin(v) == B0 <=> loThr <= v < hiThr
    const float hiThr = (B0 == 31u) ? CUDART_INF_F : fkey_inv((B0 + 1u) << 27);
    const float loThr = (B0 == 0u) ? -CUDART_INF_F : fkey_inv(B0 << 27);

    // ---- Pass 2 (L2 re-read, fused): write output, collect candidates + fine hist ----
    #pragma unroll 1
    for (int i = tid; i < V4; i += NT) {
        float4 v = zr[i];
        float4 o;
        o.x = (v.x >= hiThr) ? v.x : 0.0f;
        o.y = (v.y >= hiThr) ? v.y : 0.0f;
        o.z = (v.z >= hiThr) ? v.z : 0.0f;
        o.w = (v.w >= hiThr) ? v.w : 0.0f;
        __stcs(&orw[i], o);                     // evict-first: protect z in L2
        // Rare path (~560/row): elements in coarse bin B0
        if (v.x >= loThr && v.x < hiThr) { uint32_t p = atomicAdd(&s_cnt, 1u); if (p < CAP) { uint32_t ky = fkey(v.x); candKey[p] = ky; candIdx[p] = (uint16_t)(4*i+0); atomicAdd(&fineH[(ky >> 15) & 0xFFFu], 1u); } }
        if (v.y >= loThr && v.y < hiThr) { uint32_t p = atomicAdd(&s_cnt, 1u); if (p < CAP) { uint32_t ky = fkey(v.y); candKey[p] = ky; candIdx[p] = (uint16_t)(4*i+1); atomicAdd(&fineH[(ky >> 15) & 0xFFFu], 1u); } }
        if (v.z >= loThr && v.z < hiThr) { uint32_t p = atomicAdd(&s_cnt, 1u); if (p < CAP) { uint32_t ky = fkey(v.z); candKey[p] = ky; candIdx[p] = (uint16_t)(4*i+2); atomicAdd(&fineH[(ky >> 15) & 0xFFFu], 1u); } }
        if (v.w >= loThr && v.w < hiThr) { uint32_t p = atomicAdd(&s_cnt, 1u); if (p < CAP) { uint32_t ky = fkey(v.w); candKey[p] = ky; candIdx[p] = (uint16_t)(4*i+3); atomicAdd(&fineH[(ky >> 15) & 0xFFFu], 1u); } }
    }
    __syncthreads();
    const uint32_t n = min(s_cnt, (uint32_t)CAP);
    const uint32_t needC = k - A0;              // winners to pick among candidates

    // ---- Fine suffix scan (4096 bins, 16-warp) to find fine bin B1 ----
    const int base = tid * BPTF;
    uint32_t s = 0;
    #pragma unroll
    for (int j = 0; j < BPTF; j++) s += fineH[base + j];
    uint32_t inc = s;
    #pragma unroll
    for (int off = 1; off < 32; off <<= 1) {
        uint32_t o = __shfl_down_sync(0xFFFFFFFFu, inc, off);
        if (lane + off < 32) inc += o;
    }
    if (lane == 0) warpTot[wid] = inc;
    __syncthreads();
    uint32_t ws = 0;
    #pragma unroll
    for (int w = 0; w < NW; w++) if (w > wid) ws += warpTot[w];
    uint32_t abv  = ws + (inc - s);
    uint32_t incl = ws + inc;
    if (abv < needC && incl >= needC) {         // exactly one thread matches
        uint32_t a = abv;
        #pragma unroll
        for (int j = BPTF - 1; j >= 0; j--) {
            uint32_t c = fineH[base + j];
            if (a + c >= needC) { s_B1 = (uint32_t)(base + j); s_A1 = a; break; }
            a += c;
        }
    }
    __syncthreads();
    const uint32_t B1    = s_B1;
    const uint32_t need2 = needC - s_A1;        // winners inside fine bin B1

    // ---- Winners: fine-bin > B1 write directly; exact rank inside fine bin B1 ----
    for (uint32_t j = tid; j < n; j += NT) {
        uint32_t kj = candKey[j];
        uint32_t fb = (kj >> 15) & 0xFFFu;
        if (fb > B1) {
            orow[candIdx[j]] = fkey_inv(kj);
        } else if (fb == B1) {
            uint32_t ij = candIdx[j];
            uint32_t r = 0;
            for (uint32_t m = 0; m < n; m++) {
                uint32_t km = candKey[m];
                if (((km >> 15) & 0xFFFu) == B1)
                    r += (km > kj) || (km == kj && candIdx[m] < ij);
            }
            if (r < need2) orow[ij] = fkey_inv(kj);
        }
    }
}

extern "C" void kernel_launch(void* const* d_in, const int* in_sizes, int n_in,
                              void* d_out, int out_size) {
    const float* z   = (const float*)d_in[0];
    const int*   kin = (n_in >= 2) ? (const int*)d_in[1] : nullptr;
    float*       out = (float*)d_out;
    int rows = in_sizes[0] / COLS;   // 8192
    topk_scatter_kernel<<<rows, NT>>>(z, kin, out);
}

// round 9
// speedup vs baseline: 1.7968x; 1.7968x over previous
#include <cuda_runtime.h>
#include <cstdint>
#include <math_constants.h>

#define COLS   24576
#define V4     (COLS / 4)      // 6144 float4 per row
#define NBINS  8192            // top-13 bits of monotonic key
#define NT     512             // threads per CTA
#define BPT    (NBINS / NT)    // 16 bins per thread
#define NW     (NT / 32)       // 16 warps
#define CAP    1024            // candidate buffer capacity
#define FILT   2.0f            // only v >= FILT get histogram atomics (fast path)

// Order-preserving float->uint key: larger float => larger key.
__device__ __forceinline__ uint32_t fkey(float f) {
    uint32_t u = __float_as_uint(f);
    return u ^ (uint32_t)(((int32_t)u >> 31) | (int32_t)0x80000000);
}
// Inverse of fkey.
__device__ __forceinline__ float fkey_inv(uint32_t key) {
    uint32_t u = key ^ ((key & 0x80000000u) ? 0x80000000u : 0xFFFFFFFFu);
    return __uint_as_float(u);
}

__global__ __launch_bounds__(NT, 4) void topk_scatter_kernel(
    const float* __restrict__ z,
    const int*   __restrict__ kin,
    float*       __restrict__ out)
{
    __shared__ uint32_t hist[NBINS];       // 32 KB
    __shared__ uint32_t candKey[CAP];      // 4 KB
    __shared__ uint16_t candIdx[CAP];      // 2 KB
    __shared__ uint32_t warpTot[NW];
    __shared__ uint32_t s_binB, s_above, s_cnt, s_high;

    const int tid  = threadIdx.x;
    const int lane = tid & 31;
    const int wid  = tid >> 5;
    const int row  = blockIdx.x;
    const uint32_t k = (uint32_t)(kin ? *kin : 64);

    const float4* zr  = reinterpret_cast<const float4*>(z) + (size_t)row * V4;
    float4*       orw = reinterpret_cast<float4*>(out)     + (size_t)row * V4;
    float*        orow = out + (size_t)row * COLS;

    for (int i = tid; i < NBINS; i += NT) hist[i] = 0;
    if (tid == 0) { s_cnt = 0; s_high = 0; }
    __syncthreads();

    // ---- Pass 1 (HBM read): histogram only the far upper tail (v >= FILT) ----
    uint32_t myHigh = 0;
    #pragma unroll 1
    for (int i = tid; i < V4; i += NT) {
        float4 v = zr[i];
        if (v.x >= FILT) { atomicAdd(&hist[fkey(v.x) >> 19], 1u); myHigh++; }
        if (v.y >= FILT) { atomicAdd(&hist[fkey(v.y) >> 19], 1u); myHigh++; }
        if (v.z >= FILT) { atomicAdd(&hist[fkey(v.z) >> 19], 1u); myHigh++; }
        if (v.w >= FILT) { atomicAdd(&hist[fkey(v.w) >> 19], 1u); myHigh++; }
    }
    // block-reduce the high-element count
    #pragma unroll
    for (int off = 16; off > 0; off >>= 1)
        myHigh += __shfl_down_sync(0xFFFFFFFFu, myHigh, off);
    if (lane == 0) atomicAdd(&s_high, myHigh);
    __syncthreads();

    // ---- Slow path (correctness only; never taken for this data): histogram rest ----
    if (s_high < k) {
        #pragma unroll 1
        for (int i = tid; i < V4; i += NT) {
            float4 v = zr[i];
            if (!(v.x >= FILT)) atomicAdd(&hist[fkey(v.x) >> 19], 1u);
            if (!(v.y >= FILT)) atomicAdd(&hist[fkey(v.y) >> 19], 1u);
            if (!(v.z >= FILT)) atomicAdd(&hist[fkey(v.z) >> 19], 1u);
            if (!(v.w >= FILT)) atomicAdd(&hist[fkey(v.w) >> 19], 1u);
        }
        __syncthreads();
    }

    // ---- Warp-shuffle suffix scan to locate the rank-k bin ----
    const int base = tid * BPT;
    uint32_t s = 0;
    #pragma unroll
    for (int j = 0; j < BPT; j++) s += hist[base + j];
    uint32_t inc = s;                               // inclusive suffix within warp
    #pragma unroll
    for (int off = 1; off < 32; off <<= 1) {
        uint32_t o = __shfl_down_sync(0xFFFFFFFFu, inc, off);
        if (lane + off < 32) inc += o;
    }
    if (lane == 0) warpTot[wid] = inc;              // warp total
    __syncthreads();
    uint32_t ws = 0;
    #pragma unroll
    for (int w = 0; w < NW; w++) if (w > wid) ws += warpTot[w];
    uint32_t abv  = ws + (inc - s);                 // strictly above this thread's bins
    uint32_t incl = ws + inc;
    if (abv < k && incl >= k) {                     // exactly one thread matches
        uint32_t a = abv;
        #pragma unroll
        for (int j = BPT - 1; j >= 0; j--) {
            uint32_t c = hist[base + j];
            if (a + c >= k) { s_binB = (uint32_t)(base + j); s_above = a; break; }
            a += c;
        }
    }
    __syncthreads();
    const uint32_t binB = s_binB;
    const uint32_t need = k - s_above;              // winners inside threshold bin

    // Float thresholds: bin(v) > binB  <=>  v >= hiThr ;  bin(v)==binB <=> loThr <= v < hiThr
    const float hiThr = (binB == NBINS - 1u) ? CUDART_INF_F : fkey_inv((binB + 1u) << 19);
    const float loThr = fkey_inv(binB << 19);

    // ---- Pass 2 (fused, L2 re-read): write output, collect candidates ----
    #pragma unroll 1
    for (int i = tid; i < V4; i += NT) {
        float4 v = zr[i];
        float4 o;
        o.x = (v.x >= hiThr) ? v.x : 0.0f;
        o.y = (v.y >= hiThr) ? v.y : 0.0f;
        o.z = (v.z >= hiThr) ? v.z : 0.0f;
        o.w = (v.w >= hiThr) ? v.w : 0.0f;
        __stcs(&orw[i], o);                         // evict-first: protect z in L2
        // Rare path: candidates in the threshold bin (~25 per row)
        if (v.x >= loThr && v.x < hiThr) { uint32_t p = atomicAdd(&s_cnt, 1u); if (p < CAP) { candKey[p] = fkey(v.x); candIdx[p] = (uint16_t)(4*i+0); } }
        if (v.y >= loThr && v.y < hiThr) { uint32_t p = atomicAdd(&s_cnt, 1u); if (p < CAP) { candKey[p] = fkey(v.y); candIdx[p] = (uint16_t)(4*i+1); } }
        if (v.z >= loThr && v.z < hiThr) { uint32_t p = atomicAdd(&s_cnt, 1u); if (p < CAP) { candKey[p] = fkey(v.z); candIdx[p] = (uint16_t)(4*i+2); } }
        if (v.w >= loThr && v.w < hiThr) { uint32_t p = atomicAdd(&s_cnt, 1u); if (p < CAP) { candKey[p] = fkey(v.w); candIdx[p] = (uint16_t)(4*i+3); } }
    }
    __syncthreads();
    const uint32_t n = min(s_cnt, (uint32_t)CAP);

    // ---- Exact rank among candidates (key desc, idx asc); winners fix up output ----
    for (uint32_t j = tid; j < n; j += NT) {
        uint32_t kj = candKey[j];
        uint32_t ij = candIdx[j];
        uint32_t r = 0;
        for (uint32_t m = 0; m < n; m++) {
            uint32_t km = candKey[m];
            r += (km > kj) || (km == kj && candIdx[m] < ij);
        }
        if (r < need) orow[ij] = fkey_inv(kj);      // exactly `need` winners
    }
}

extern "C" void kernel_launch(void* const* d_in, const int* in_sizes, int n_in,
                              void* d_out, int out_size) {
    const float* z   = (const float*)d_in[0];
    const int*   kin = (n_in >= 2) ? (const int*)d_in[1] : nullptr;
    float*       out = (float*)d_out;
    int rows = in_sizes[0] / COLS;   // 8192
    topk_scatter_kernel<<<rows, NT>>>(z, kin, out);
}

// round 10
// speedup vs baseline: 2.0314x; 1.1306x over previous
#include <cuda_runtime.h>
#include <cstdint>
#include <math_constants.h>

#define COLS   24576
#define V4     (COLS / 4)      // 6144 float4 per row
#define NBINS  8192            // top-13 bits of monotonic key
#define NT     512             // threads per CTA
#define BPT    (NBINS / NT)    // 16 bins per thread
#define NW     (NT / 32)       // 16 warps
#define CAP    1024            // candidate buffer capacity
#define FILT   2.0f            // only v >= FILT get histogram atomics (fast path)

// Order-preserving float->uint key: larger float => larger key.
__device__ __forceinline__ uint32_t fkey(float f) {
    uint32_t u = __float_as_uint(f);
    return u ^ (uint32_t)(((int32_t)u >> 31) | (int32_t)0x80000000);
}
// Inverse of fkey.
__device__ __forceinline__ float fkey_inv(uint32_t key) {
    uint32_t u = key ^ ((key & 0x80000000u) ? 0x80000000u : 0xFFFFFFFFu);
    return __uint_as_float(u);
}

__global__ __launch_bounds__(NT, 4) void topk_scatter_kernel(
    const float* __restrict__ z,
    const int*   __restrict__ kin,
    float*       __restrict__ out)
{
    __shared__ uint32_t hist[NBINS];       // 32 KB
    __shared__ uint32_t candKey[CAP];      // 4 KB
    __shared__ uint16_t candIdx[CAP];      // 2 KB
    __shared__ uint32_t warpTot[NW];
    __shared__ uint32_t s_binB, s_above, s_cnt, s_high;

    const int tid  = threadIdx.x;
    const int lane = tid & 31;
    const int wid  = tid >> 5;
    const int row  = blockIdx.x;
    const uint32_t k = (uint32_t)(kin ? *kin : 64);

    const float4* zr  = reinterpret_cast<const float4*>(z) + (size_t)row * V4;
    float4*       orw = reinterpret_cast<float4*>(out)     + (size_t)row * V4;
    float*        orow = out + (size_t)row * COLS;

    for (int i = tid; i < NBINS; i += NT) hist[i] = 0;
    if (tid == 0) { s_cnt = 0; s_high = 0; }
    __syncthreads();

    // ---- Pass 1 (HBM read): MLP=2, histogram only the far upper tail ----
    uint32_t myHigh = 0;
    #pragma unroll 1
    for (int i = tid; i < V4; i += 2 * NT) {        // V4 = 6 * (2*NT): exact
        float4 a = zr[i];
        float4 b = zr[i + NT];
        if (a.x >= FILT) { atomicAdd(&hist[fkey(a.x) >> 19], 1u); myHigh++; }
        if (a.y >= FILT) { atomicAdd(&hist[fkey(a.y) >> 19], 1u); myHigh++; }
        if (a.z >= FILT) { atomicAdd(&hist[fkey(a.z) >> 19], 1u); myHigh++; }
        if (a.w >= FILT) { atomicAdd(&hist[fkey(a.w) >> 19], 1u); myHigh++; }
        if (b.x >= FILT) { atomicAdd(&hist[fkey(b.x) >> 19], 1u); myHigh++; }
        if (b.y >= FILT) { atomicAdd(&hist[fkey(b.y) >> 19], 1u); myHigh++; }
        if (b.z >= FILT) { atomicAdd(&hist[fkey(b.z) >> 19], 1u); myHigh++; }
        if (b.w >= FILT) { atomicAdd(&hist[fkey(b.w) >> 19], 1u); myHigh++; }
    }
    // block-reduce the high-element count
    #pragma unroll
    for (int off = 16; off > 0; off >>= 1)
        myHigh += __shfl_down_sync(0xFFFFFFFFu, myHigh, off);
    if (lane == 0) atomicAdd(&s_high, myHigh);
    __syncthreads();

    // ---- Slow path (correctness only; never taken for this data): histogram rest ----
    if (s_high < k) {
        #pragma unroll 1
        for (int i = tid; i < V4; i += NT) {
            float4 v = zr[i];
            if (!(v.x >= FILT)) atomicAdd(&hist[fkey(v.x) >> 19], 1u);
            if (!(v.y >= FILT)) atomicAdd(&hist[fkey(v.y) >> 19], 1u);
            if (!(v.z >= FILT)) atomicAdd(&hist[fkey(v.z) >> 19], 1u);
            if (!(v.w >= FILT)) atomicAdd(&hist[fkey(v.w) >> 19], 1u);
        }
        __syncthreads();
    }

    // ---- Warp-shuffle suffix scan to locate the rank-k bin ----
    const int base = tid * BPT;
    uint32_t s = 0;
    #pragma unroll
    for (int j = 0; j < BPT; j++) s += hist[base + j];
    uint32_t inc = s;                               // inclusive suffix within warp
    #pragma unroll
    for (int off = 1; off < 32; off <<= 1) {
        uint32_t o = __shfl_down_sync(0xFFFFFFFFu, inc, off);
        if (lane + off < 32) inc += o;
    }
    if (lane == 0) warpTot[wid] = inc;              // warp total
    __syncthreads();
    uint32_t ws = 0;
    #pragma unroll
    for (int w = 0; w < NW; w++) if (w > wid) ws += warpTot[w];
    uint32_t abv  = ws + (inc - s);                 // strictly above this thread's bins
    uint32_t incl = ws + inc;
    if (abv < k && incl >= k) {                     // exactly one thread matches
        uint32_t a = abv;
        #pragma unroll
        for (int j = BPT - 1; j >= 0; j--) {
            uint32_t c = hist[base + j];
            if (a + c >= k) { s_binB = (uint32_t)(base + j); s_above = a; break; }
            a += c;
        }
    }
    __syncthreads();
    const uint32_t binB = s_binB;
    const uint32_t need = k - s_above;              // winners inside threshold bin

    // Float thresholds: bin(v) > binB  <=>  v >= hiThr ;  bin(v)==binB <=> loThr <= v < hiThr
    const float hiThr = (binB == NBINS - 1u) ? CUDART_INF_F : fkey_inv((binB + 1u) << 19);
    const float loThr = fkey_inv(binB << 19);

    // ---- Pass 2 (fused, L2 re-read, MLP=2): write output, collect candidates ----
    #pragma unroll 1
    for (int i = tid; i < V4; i += 2 * NT) {
        float4 a = zr[i];
        float4 b = zr[i + NT];
        float4 oa, ob;
        oa.x = (a.x >= hiThr) ? a.x : 0.0f;
        oa.y = (a.y >= hiThr) ? a.y : 0.0f;
        oa.z = (a.z >= hiThr) ? a.z : 0.0f;
        oa.w = (a.w >= hiThr) ? a.w : 0.0f;
        ob.x = (b.x >= hiThr) ? b.x : 0.0f;
        ob.y = (b.y >= hiThr) ? b.y : 0.0f;
        ob.z = (b.z >= hiThr) ? b.z : 0.0f;
        ob.w = (b.w >= hiThr) ? b.w : 0.0f;
        __stcs(&orw[i],      oa);                   // evict-first: protect z in L2
        __stcs(&orw[i + NT], ob);
        // Rare path: candidates in the threshold bin (~25 per row)
        if (a.x >= loThr && a.x < hiThr) { uint32_t p = atomicAdd(&s_cnt, 1u); if (p < CAP) { candKey[p] = fkey(a.x); candIdx[p] = (uint16_t)(4*i+0); } }
        if (a.y >= loThr && a.y < hiThr) { uint32_t p = atomicAdd(&s_cnt, 1u); if (p < CAP) { candKey[p] = fkey(a.y); candIdx[p] = (uint16_t)(4*i+1); } }
        if (a.z >= loThr && a.z < hiThr) { uint32_t p = atomicAdd(&s_cnt, 1u); if (p < CAP) { candKey[p] = fkey(a.z); candIdx[p] = (uint16_t)(4*i+2); } }
        if (a.w >= loThr && a.w < hiThr) { uint32_t p = atomicAdd(&s_cnt, 1u); if (p < CAP) { candKey[p] = fkey(a.w); candIdx[p] = (uint16_t)(4*i+3); } }
        if (b.x >= loThr && b.x < hiThr) { uint32_t p = atomicAdd(&s_cnt, 1u); if (p < CAP) { candKey[p] = fkey(b.x); candIdx[p] = (uint16_t)(4*(i+NT)+0); } }
        if (b.y >= loThr && b.y < hiThr) { uint32_t p = atomicAdd(&s_cnt, 1u); if (p < CAP) { candKey[p] = fkey(b.y); candIdx[p] = (uint16_t)(4*(i+NT)+1); } }
        if (b.z >= loThr && b.z < hiThr) { uint32_t p = atomicAdd(&s_cnt, 1u); if (p < CAP) { candKey[p] = fkey(b.z); candIdx[p] = (uint16_t)(4*(i+NT)+2); } }
        if (b.w >= loThr && b.w < hiThr) { uint32_t p = atomicAdd(&s_cnt, 1u); if (p < CAP) { candKey[p] = fkey(b.w); candIdx[p] = (uint16_t)(4*(i+NT)+3); } }
    }
    __syncthreads();
    const uint32_t n = min(s_cnt, (uint32_t)CAP);

    // ---- Exact rank among candidates (key desc, idx asc); winners fix up output ----
    for (uint32_t j = tid; j < n; j += NT) {
        uint32_t kj = candKey[j];
        uint32_t ij = candIdx[j];
        uint32_t r = 0;
        for (uint32_t m = 0; m < n; m++) {
            uint32_t km = candKey[m];
            r += (km > kj) || (km == kj && candIdx[m] < ij);
        }
        if (r < need) orow[ij] = fkey_inv(kj);      // exactly `need` winners
    }
}

extern "C" void kernel_launch(void* const* d_in, const int* in_sizes, int n_in,
                              void* d_out, int out_size) {
    const float* z   = (const float*)d_in[0];
    const int*   kin = (n_in >= 2) ? (const int*)d_in[1] : nullptr;
    float*       out = (float*)d_out;
    int rows = in_sizes[0] / COLS;   // 8192
    topk_scatter_kernel<<<rows, NT>>>(z, kin, out);
}

// round 11
// speedup vs baseline: 2.0572x; 1.0127x over previous
#include <cuda_runtime.h>
#include <cstdint>
#include <math_constants.h>

#define COLS   24576
#define V4     (COLS / 4)      // 6144 float4 per row
#define NBINS  8192            // top-13 bits of monotonic key
#define NT     512             // threads per CTA
#define BPT    (NBINS / NT)    // 16 bins per thread
#define NW     (NT / 32)       // 16 warps
#define CAP    1024            // candidate buffer capacity
#define FILT   2.0f            // only v >= FILT get histogram atomics (fast path)

// Order-preserving float->uint key: larger float => larger key.
__device__ __forceinline__ uint32_t fkey(float f) {
    uint32_t u = __float_as_uint(f);
    return u ^ (uint32_t)(((int32_t)u >> 31) | (int32_t)0x80000000);
}
// Inverse of fkey.
__device__ __forceinline__ float fkey_inv(uint32_t key) {
    uint32_t u = key ^ ((key & 0x80000000u) ? 0x80000000u : 0xFFFFFFFFu);
    return __uint_as_float(u);
}

__global__ __launch_bounds__(NT, 4) void topk_scatter_kernel(
    const float* __restrict__ z,
    const int*   __restrict__ kin,
    float*       __restrict__ out)
{
    __shared__ uint32_t hist[NBINS];       // 32 KB
    __shared__ uint32_t candKey[CAP];      // 4 KB
    __shared__ uint16_t candIdx[CAP];      // 2 KB
    __shared__ uint32_t warpTot[NW];
    __shared__ uint32_t s_binB, s_above, s_cnt, s_high;

    const int tid  = threadIdx.x;
    const int lane = tid & 31;
    const int wid  = tid >> 5;
    const int row  = blockIdx.x;
    const uint32_t k = (uint32_t)(kin ? *kin : 64);

    const float4* zr  = reinterpret_cast<const float4*>(z) + (size_t)row * V4;
    float4*       orw = reinterpret_cast<float4*>(out)     + (size_t)row * V4;
    float*        orow = out + (size_t)row * COLS;

    for (int i = tid; i < NBINS; i += NT) hist[i] = 0;
    if (tid == 0) { s_cnt = 0; s_high = 0; }
    __syncthreads();

    // ---- Pass 1 (HBM read, MLP=3, L2-only): histogram only the far upper tail ----
    uint32_t myHigh = 0;
    #pragma unroll 1
    for (int i = tid; i < V4; i += 3 * NT) {        // V4 = 4 * (3*NT): exact
        float4 a = __ldcg(&zr[i]);
        float4 b = __ldcg(&zr[i + NT]);
        float4 c = __ldcg(&zr[i + 2 * NT]);
        if (a.x >= FILT) { atomicAdd(&hist[fkey(a.x) >> 19], 1u); myHigh++; }
        if (a.y >= FILT) { atomicAdd(&hist[fkey(a.y) >> 19], 1u); myHigh++; }
        if (a.z >= FILT) { atomicAdd(&hist[fkey(a.z) >> 19], 1u); myHigh++; }
        if (a.w >= FILT) { atomicAdd(&hist[fkey(a.w) >> 19], 1u); myHigh++; }
        if (b.x >= FILT) { atomicAdd(&hist[fkey(b.x) >> 19], 1u); myHigh++; }
        if (b.y >= FILT) { atomicAdd(&hist[fkey(b.y) >> 19], 1u); myHigh++; }
        if (b.z >= FILT) { atomicAdd(&hist[fkey(b.z) >> 19], 1u); myHigh++; }
        if (b.w >= FILT) { atomicAdd(&hist[fkey(b.w) >> 19], 1u); myHigh++; }
        if (c.x >= FILT) { atomicAdd(&hist[fkey(c.x) >> 19], 1u); myHigh++; }
        if (c.y >= FILT) { atomicAdd(&hist[fkey(c.y) >> 19], 1u); myHigh++; }
        if (c.z >= FILT) { atomicAdd(&hist[fkey(c.z) >> 19], 1u); myHigh++; }
        if (c.w >= FILT) { atomicAdd(&hist[fkey(c.w) >> 19], 1u); myHigh++; }
    }
    // block-reduce the high-element count
    #pragma unroll
    for (int off = 16; off > 0; off >>= 1)
        myHigh += __shfl_down_sync(0xFFFFFFFFu, myHigh, off);
    if (lane == 0) atomicAdd(&s_high, myHigh);
    __syncthreads();

    // ---- Slow path (correctness only; never taken for this data): histogram rest ----
    if (s_high < k) {
        #pragma unroll 1
        for (int i = tid; i < V4; i += NT) {
            float4 v = zr[i];
            if (!(v.x >= FILT)) atomicAdd(&hist[fkey(v.x) >> 19], 1u);
            if (!(v.y >= FILT)) atomicAdd(&hist[fkey(v.y) >> 19], 1u);
            if (!(v.z >= FILT)) atomicAdd(&hist[fkey(v.z) >> 19], 1u);
            if (!(v.w >= FILT)) atomicAdd(&hist[fkey(v.w) >> 19], 1u);
        }
        __syncthreads();
    }

    // ---- Warp-shuffle suffix scan to locate the rank-k bin ----
    const int base = tid * BPT;
    uint32_t s = 0;
    #pragma unroll
    for (int j = 0; j < BPT; j++) s += hist[base + j];
    uint32_t inc = s;                               // inclusive suffix within warp
    #pragma unroll
    for (int off = 1; off < 32; off <<= 1) {
        uint32_t o = __shfl_down_sync(0xFFFFFFFFu, inc, off);
        if (lane + off < 32) inc += o;
    }
    if (lane == 0) warpTot[wid] = inc;              // warp total
    __syncthreads();
    uint32_t ws = 0;
    #pragma unroll
    for (int w = 0; w < NW; w++) if (w > wid) ws += warpTot[w];
    uint32_t abv  = ws + (inc - s);                 // strictly above this thread's bins
    uint32_t incl = ws + inc;
    if (abv < k && incl >= k) {                     // exactly one thread matches
        uint32_t a = abv;
        #pragma unroll
        for (int j = BPT - 1; j >= 0; j--) {
            uint32_t c = hist[base + j];
            if (a + c >= k) { s_binB = (uint32_t)(base + j); s_above = a; break; }
            a += c;
        }
    }
    __syncthreads();
    const uint32_t binB = s_binB;
    const uint32_t need = k - s_above;              // winners inside threshold bin

    // Float thresholds: bin(v) > binB  <=>  v >= hiThr ;  bin(v)==binB <=> loThr <= v < hiThr
    const float hiThr = (binB == NBINS - 1u) ? CUDART_INF_F : fkey_inv((binB + 1u) << 19);
    const float loThr = fkey_inv(binB << 19);

    // ---- Pass 2 (fused, L2 re-read evict-first, MLP=2): write output + candidates ----
    #pragma unroll 1
    for (int i = tid; i < V4; i += 2 * NT) {        // V4 = 6 * (2*NT): exact
        float4 a = __ldcs(&zr[i]);
        float4 b = __ldcs(&zr[i + NT]);
        float4 oa, ob;
        oa.x = (a.x >= hiThr) ? a.x : 0.0f;
        oa.y = (a.y >= hiThr) ? a.y : 0.0f;
        oa.z = (a.z >= hiThr) ? a.z : 0.0f;
        oa.w = (a.w >= hiThr) ? a.w : 0.0f;
        ob.x = (b.x >= hiThr) ? b.x : 0.0f;
        ob.y = (b.y >= hiThr) ? b.y : 0.0f;
        ob.z = (b.z >= hiThr) ? b.z : 0.0f;
        ob.w = (b.w >= hiThr) ? b.w : 0.0f;
        __stcs(&orw[i],      oa);                   // evict-first: protect z in L2
        __stcs(&orw[i + NT], ob);
        // Rare path: candidates in the threshold bin (~25 per row)
        if (a.x >= loThr && a.x < hiThr) { uint32_t p = atomicAdd(&s_cnt, 1u); if (p < CAP) { candKey[p] = fkey(a.x); candIdx[p] = (uint16_t)(4*i+0); } }
        if (a.y >= loThr && a.y < hiThr) { uint32_t p = atomicAdd(&s_cnt, 1u); if (p < CAP) { candKey[p] = fkey(a.y); candIdx[p] = (uint16_t)(4*i+1); } }
        if (a.z >= loThr && a.z < hiThr) { uint32_t p = atomicAdd(&s_cnt, 1u); if (p < CAP) { candKey[p] = fkey(a.z); candIdx[p] = (uint16_t)(4*i+2); } }
        if (a.w >= loThr && a.w < hiThr) { uint32_t p = atomicAdd(&s_cnt, 1u); if (p < CAP) { candKey[p] = fkey(a.w); candIdx[p] = (uint16_t)(4*i+3); } }
        if (b.x >= loThr && b.x < hiThr) { uint32_t p = atomicAdd(&s_cnt, 1u); if (p < CAP) { candKey[p] = fkey(b.x); candIdx[p] = (uint16_t)(4*(i+NT)+0); } }
        if (b.y >= loThr && b.y < hiThr) { uint32_t p = atomicAdd(&s_cnt, 1u); if (p < CAP) { candKey[p] = fkey(b.y); candIdx[p] = (uint16_t)(4*(i+NT)+1); } }
        if (b.z >= loThr && b.z < hiThr) { uint32_t p = atomicAdd(&s_cnt, 1u); if (p < CAP) { candKey[p] = fkey(b.z); candIdx[p] = (uint16_t)(4*(i+NT)+2); } }
        if (b.w >= loThr && b.w < hiThr) { uint32_t p = atomicAdd(&s_cnt, 1u); if (p < CAP) { candKey[p] = fkey(b.w); candIdx[p] = (uint16_t)(4*(i+NT)+3); } }
    }
    __syncthreads();
    const uint32_t n = min(s_cnt, (uint32_t)CAP);

    // ---- Exact rank among candidates (key desc, idx asc); winners fix up output ----
    for (uint32_t j = tid; j < n; j += NT) {
        uint32_t kj = candKey[j];
        uint32_t ij = candIdx[j];
        uint32_t r = 0;
        for (uint32_t m = 0; m < n; m++) {
            uint32_t km = candKey[m];
            r += (km > kj) || (km == kj && candIdx[m] < ij);
        }
        if (r < need) orow[ij] = fkey_inv(kj);      // exactly `need` winners
    }
}

extern "C" void kernel_launch(void* const* d_in, const int* in_sizes, int n_in,
                              void* d_out, int out_size) {
    const float* z   = (const float*)d_in[0];
    const int*   kin = (n_in >= 2) ? (const int*)d_in[1] : nullptr;
    float*       out = (float*)d_out;
    int rows = in_sizes[0] / COLS;   // 8192
    topk_scatter_kernel<<<rows, NT>>>(z, kin, out);
}